// round 15
// baseline (speedup 1.0000x reference)
#include <cuda_runtime.h>

// IIR filterbank (DF2T, order 4), overlap-save, cp.async 4-deep pipelined
// warp-transposed smem staging. x: (128,4,65536) f32; b,a: (4,5); out = shape(x).
//
// R8: register double-buffer -> 55.4us (DRAM 66.8%, issue 35%, 265MB HBM =
// at the 256MB traffic floor). Still latency-bound: 14 warps/SM, 4KB/warp in
// flight. R9-R15: LDGSTS (cp.async) ring of 4 tile buffers -> 12KB/warp in
// flight, no register buffers (regs 96->~56), outputs computed in-place in
// smem. 2 warps/block keeps 4x4.6KB ring under the 48KB static smem limit;
// warps/SM residency unchanged (launch-limited at 2048 warps).
// R15 = sixth resubmission (R9-R14 all GPUAcquisitionTimeout; never ran).
//
// WARMUP=192, poles at r=0.9: state error ~1.7e-9; measured rel_err 2.07e-5
// (fp32-rounding dominated). Chunk 0 exact via post-warmup state reset.

#define T_LEN     65536
#define CHUNK_L   512
#define WARMUP    192
#define TILE      32
#define RSTRIDE   36                       // padded row stride (words)
#define BUF_W     (32 * RSTRIDE)           // words per tile buffer (1152)
#define NBUF      4
#define WPB       2
#define THREADS   64
#define WARPS_PER_CH  ((T_LEN / CHUNK_L) / 32)   // 4
#define NTILES    ((WARMUP + CHUNK_L) / TILE)    // 22
#define WTILES    (WARMUP / TILE)                // 6

#define IIR_STEP(xn, yn) do {                              \
        float xv_ = (xn);                                  \
        float y_  = fmaf(b0, xv_, z0);                     \
        z0 = fmaf(na1, y_, fmaf(b1, xv_, z1));             \
        z1 = fmaf(na2, y_, fmaf(b2, xv_, z2));             \
        z2 = fmaf(na3, y_, fmaf(b3, xv_, z3));             \
        z3 = fmaf(na4, y_, b4 * xv_);                      \
        (yn) = y_;                                         \
    } while (0)

__global__ void __launch_bounds__(THREADS)
iir_filterbank_kernel(const float* __restrict__ x,
                      const float* __restrict__ bc,
                      const float* __restrict__ ac,
                      float* __restrict__ y)
{
    __shared__ __align__(16) float sm_all[WPB][NBUF][BUF_W];  // 36.9KB

    const int lane = threadIdx.x & 31;
    const int wib  = threadIdx.x >> 5;
    const int w    = blockIdx.x * WPB + wib;
    const int channel     = w / WARPS_PER_CH;
    const int first_chunk = (w % WARPS_PER_CH) * 32;
    const int f    = channel & 3;

    float* sm = &sm_all[wib][0][0];
    const unsigned sm_base = (unsigned)__cvta_generic_to_shared(sm);

    float inv = 1.0f / __ldg(&ac[f*5+0]);
    float b0  =  __ldg(&bc[f*5+0]) * inv;
    float b1  =  __ldg(&bc[f*5+1]) * inv;
    float b2  =  __ldg(&bc[f*5+2]) * inv;
    float b3  =  __ldg(&bc[f*5+3]) * inv;
    float b4  =  __ldg(&bc[f*5+4]) * inv;
    float na1 = -__ldg(&ac[f*5+1]) * inv;
    float na2 = -__ldg(&ac[f*5+2]) * inv;
    float na3 = -__ldg(&ac[f*5+3]) * inv;
    float na4 = -__ldg(&ac[f*5+4]) * inv;

    const long long ch_base = (long long)channel * T_LEN;
    const int sub   = lane & 7;    // 16B slot within the 128B tile row
    const int rbase = lane >> 3;   // row group 0..3

    // Async-stage tile i (samples [chunk_r - WARMUP + i*32, +32) per row r)
    // into ring buffer i&3, already transposed for per-row consumption.
    // Chunk 0 has no prefix: shift its warmup reads into [0,WARMUP) (values
    // irrelevant — its state is reset to zero after the warmup tiles).
#define STAGE_TILE(i)                                                         \
    do {                                                                      \
        if ((i) < NTILES) {                                                   \
            _Pragma("unroll")                                                 \
            for (int s_ = 0; s_ < 8; ++s_) {                                  \
                int r_ = s_ * 4 + rbase;                                      \
                long long g_ = ch_base                                        \
                    + (long long)(first_chunk + r_) * CHUNK_L                 \
                    - WARMUP + (long long)(i) * TILE + sub * 4;               \
                if (first_chunk + r_ == 0 && (i) < WTILES) g_ += WARMUP;      \
                unsigned d_ = sm_base                                         \
                    + (((i) & 3) * BUF_W + r_ * RSTRIDE + sub * 4) * 4u;      \
                asm volatile("cp.async.cg.shared.global [%0], [%1], 16;"      \
                             :: "r"(d_), "l"(x + g_));                        \
            }                                                                 \
        }                                                                     \
        asm volatile("cp.async.commit_group;");                               \
    } while (0)

    float z0 = 0.f, z1 = 0.f, z2 = 0.f, z3 = 0.f;

    STAGE_TILE(0); STAGE_TILE(1); STAGE_TILE(2);

    #pragma unroll 1
    for (int i = 0; i < NTILES; ++i) {
        STAGE_TILE(i + 3);                       // issue before wait: overlap
        asm volatile("cp.async.wait_group 3;");  // tile i landed
        __syncwarp();                            // cross-lane visibility

        float* buf = sm + (i & 3) * BUF_W;

        if (i < WTILES) {
            #pragma unroll
            for (int j = 0; j < 8; ++j) {
                float4 u = *(const float4*)&buf[lane * RSTRIDE + j * 4];
                float sink;
                IIR_STEP(u.x, sink); IIR_STEP(u.y, sink);
                IIR_STEP(u.z, sink); IIR_STEP(u.w, sink);
                (void)sink;
            }
            if (i == WTILES - 1 && first_chunk == 0 && lane == 0) {
                z0 = z1 = z2 = z3 = 0.f;         // chunk 0: exact zero state
            }
        } else {
            // Own-row compute, outputs written in place (same lane+address).
            #pragma unroll
            for (int j = 0; j < 8; ++j) {
                float4 u = *(const float4*)&buf[lane * RSTRIDE + j * 4];
                float4 o;
                IIR_STEP(u.x, o.x); IIR_STEP(u.y, o.y);
                IIR_STEP(u.z, o.z); IIR_STEP(u.w, o.w);
                *(float4*)&buf[lane * RSTRIDE + j * 4] = o;
            }
            __syncwarp();
            #pragma unroll
            for (int s = 0; s < 8; ++s) {        // gather + coalesced stores
                int r = s * 4 + rbase;
                float4 ov = *(const float4*)&buf[r * RSTRIDE + sub * 4];
                long long g = ch_base + (long long)(first_chunk + r) * CHUNK_L
                              - WARMUP + (long long)i * TILE + sub * 4;
                __stcs((float4*)(y + g), ov);
            }
        }
        __syncwarp();   // all reads of buf i done before iter i+1 restages it
    }
#undef STAGE_TILE
}

extern "C" void kernel_launch(void* const* d_in, const int* in_sizes, int n_in,
                              void* d_out, int out_size)
{
    const float* x = (const float*)d_in[0];   // (128, 4, 65536)
    const float* b = (const float*)d_in[1];   // (4, 5)
    const float* a = (const float*)d_in[2];   // (4, 5)
    float* y = (float*)d_out;

    int n_channels = in_sizes[0] / T_LEN;         // 512
    int n_warps    = n_channels * WARPS_PER_CH;   // 2048
    int n_blocks   = n_warps / WPB;               // 1024

    iir_filterbank_kernel<<<n_blocks, THREADS>>>(x, b, a, y);
}